// round 1
// baseline (speedup 1.0000x reference)
#include <cuda_runtime.h>

// Problem constants
#define BB   2
#define SS   2048
#define DD   1024
#define HH   16
#define HD   64
#define QK_SCALE 0.125f      // 1/sqrt(64)

// ---------------- scratch (device globals; no allocation allowed) ----------
__device__ float g_qh[BB*HH*SS*HD];   // [B,H,S,HD]
__device__ float g_kh[BB*HH*SS*HD];
__device__ float g_vh[BB*HH*SS*HD];
__device__ float g_ao[BB*SS*DD];      // attention output, [B,S,D]

// ---------------------------------------------------------------------------
// Projection GEMM: Y = X @ W^T + b
//   X: [4096, 1024] row-major, W: [1024, 1024] row-major (out_features major)
// TGT: 0 -> g_qh (head-split), 1 -> g_kh, 2 -> g_vh, 3 -> Y param (plain [M,N])
// Tiling: 128x128 block, BK=16, 256 threads, 8x8 per thread.
// ---------------------------------------------------------------------------
template<int TGT>
__global__ __launch_bounds__(256) void proj_gemm(const float* __restrict__ X,
                                                 const float* __restrict__ W,
                                                 const float* __restrict__ bias,
                                                 float* __restrict__ Yp)
{
    __shared__ float As[16][132];
    __shared__ float Bs[16][132];

    const int m0 = blockIdx.y * 128;
    const int n0 = blockIdx.x * 128;
    const int tid = threadIdx.x;
    const int tx = tid & 15;
    const int ty = tid >> 4;

    float acc[8][8];
#pragma unroll
    for (int i = 0; i < 8; i++)
#pragma unroll
        for (int j = 0; j < 8; j++) acc[i][j] = 0.f;

    for (int k0 = 0; k0 < DD; k0 += 16) {
#pragma unroll
        for (int it = 0; it < 2; it++) {
            int lin = tid + it * 256;          // 0..511 float4 slots
            int row = lin >> 2;                // 0..127
            int c4  = lin & 3;                 // 0..3
            float4 av = *(const float4*)&X[(size_t)(m0 + row) * DD + k0 + c4 * 4];
            As[c4*4+0][row] = av.x; As[c4*4+1][row] = av.y;
            As[c4*4+2][row] = av.z; As[c4*4+3][row] = av.w;
            float4 bv = *(const float4*)&W[(size_t)(n0 + row) * DD + k0 + c4 * 4];
            Bs[c4*4+0][row] = bv.x; Bs[c4*4+1][row] = bv.y;
            Bs[c4*4+2][row] = bv.z; Bs[c4*4+3][row] = bv.w;
        }
        __syncthreads();

#pragma unroll
        for (int kk = 0; kk < 16; kk++) {
            float a[8], b[8];
            *(float4*)&a[0] = *(const float4*)&As[kk][ty * 8];
            *(float4*)&a[4] = *(const float4*)&As[kk][ty * 8 + 4];
            *(float4*)&b[0] = *(const float4*)&Bs[kk][tx * 8];
            *(float4*)&b[4] = *(const float4*)&Bs[kk][tx * 8 + 4];
#pragma unroll
            for (int i = 0; i < 8; i++)
#pragma unroll
                for (int j = 0; j < 8; j++)
                    acc[i][j] += a[i] * b[j];
        }
        __syncthreads();
    }

    float* out = (TGT == 0) ? g_qh : (TGT == 1) ? g_kh : (TGT == 2) ? g_vh : Yp;

#pragma unroll
    for (int i = 0; i < 8; i++) {
        int m = m0 + ty * 8 + i;
        int bb = m >> 11;          // / 2048
        int s  = m & 2047;
#pragma unroll
        for (int j = 0; j < 8; j++) {
            int n = n0 + tx * 8 + j;
            float y = acc[i][j] + bias[n];
            if (TGT < 3) {
                int h = n >> 6;    // / 64
                int d = n & 63;
                out[(((size_t)bb * HH + h) * SS + s) * HD + d] = y;
            } else {
                out[(size_t)m * DD + n] = y;
            }
        }
    }
}

// ---------------------------------------------------------------------------
// Flash attention (fp32, online softmax).
// Grid: (S/64, H, B). Block: 256 threads. 64 queries per CTA, K/V tiles of 64.
// smem: Qs[64][72] | KVs[64][72] (K then V, reused) | Ps[64][72]
// ---------------------------------------------------------------------------
#define FST 72
#define FLASH_SMEM (3 * 64 * FST * 4)

__global__ __launch_bounds__(256) void flash_kernel()
{
    extern __shared__ float sm[];
    float* Qs  = sm;
    float* KVs = sm + 64 * FST;
    float* Ps  = sm + 2 * 64 * FST;

    const int q0 = blockIdx.x * 64;
    const int h  = blockIdx.y;
    const int b  = blockIdx.z;
    const int tid = threadIdx.x;
    const int tx = tid & 15;
    const int ty = tid >> 4;

    const float* Qb = g_qh + ((size_t)(b * HH + h) * SS) * HD;
    const float* Kb = g_kh + ((size_t)(b * HH + h) * SS) * HD;
    const float* Vb = g_vh + ((size_t)(b * HH + h) * SS) * HD;

    // load + pre-scale Q tile: 64 rows x 64 d = 1024 float4 / 256 thr = 4 each
#pragma unroll
    for (int it = 0; it < 4; it++) {
        int lin = tid + it * 256;
        int row = lin >> 4;
        int c4  = lin & 15;
        float4 v = *(const float4*)&Qb[(size_t)(q0 + row) * HD + c4 * 4];
        v.x *= QK_SCALE; v.y *= QK_SCALE; v.z *= QK_SCALE; v.w *= QK_SCALE;
        *(float4*)&Qs[row * FST + c4 * 4] = v;
    }
    __syncthreads();

    float o[4][4];
    float mrow[4], lrow[4];
#pragma unroll
    for (int i = 0; i < 4; i++) {
        mrow[i] = -1e30f; lrow[i] = 0.f;
#pragma unroll
        for (int j = 0; j < 4; j++) o[i][j] = 0.f;
    }

    for (int kt = 0; kt < SS / 64; kt++) {
        const float* Kt = Kb + (size_t)(kt * 64) * HD;
        // load K tile into KVs
#pragma unroll
        for (int it = 0; it < 4; it++) {
            int lin = tid + it * 256;
            int row = lin >> 4;
            int c4  = lin & 15;
            *(float4*)&KVs[row * FST + c4 * 4] =
                *(const float4*)&Kt[(size_t)row * HD + c4 * 4];
        }
        __syncthreads();

        // S = Q K^T (rows = queries ty*4+i, cols = keys tx*4+j)
        float s[4][4];
#pragma unroll
        for (int i = 0; i < 4; i++)
#pragma unroll
            for (int j = 0; j < 4; j++) s[i][j] = 0.f;

#pragma unroll
        for (int k4 = 0; k4 < 16; k4++) {
            float4 a[4], bv[4];
#pragma unroll
            for (int i = 0; i < 4; i++)
                a[i] = *(const float4*)&Qs[(ty * 4 + i) * FST + k4 * 4];
#pragma unroll
            for (int j = 0; j < 4; j++)
                bv[j] = *(const float4*)&KVs[(tx * 4 + j) * FST + k4 * 4];
#pragma unroll
            for (int i = 0; i < 4; i++)
#pragma unroll
                for (int j = 0; j < 4; j++) {
                    s[i][j] += a[i].x * bv[j].x;
                    s[i][j] += a[i].y * bv[j].y;
                    s[i][j] += a[i].z * bv[j].z;
                    s[i][j] += a[i].w * bv[j].w;
                }
        }

        // online softmax per query row (row shared by 16 lanes)
        float corr[4];
#pragma unroll
        for (int i = 0; i < 4; i++) {
            float tm = fmaxf(fmaxf(s[i][0], s[i][1]), fmaxf(s[i][2], s[i][3]));
#pragma unroll
            for (int msk = 8; msk; msk >>= 1)
                tm = fmaxf(tm, __shfl_xor_sync(0xffffffffu, tm, msk));
            float mn = fmaxf(mrow[i], tm);
            corr[i] = __expf(mrow[i] - mn);
            mrow[i] = mn;
            float rs = 0.f;
#pragma unroll
            for (int j = 0; j < 4; j++) {
                float p = __expf(s[i][j] - mn);
                s[i][j] = p;
                rs += p;
            }
#pragma unroll
            for (int msk = 8; msk; msk >>= 1)
                rs += __shfl_xor_sync(0xffffffffu, rs, msk);
            lrow[i] = lrow[i] * corr[i] + rs;
        }

        // stage P
#pragma unroll
        for (int i = 0; i < 4; i++)
            *(float4*)&Ps[(ty * 4 + i) * FST + tx * 4] =
                make_float4(s[i][0], s[i][1], s[i][2], s[i][3]);
        __syncthreads();   // K reads + P writes done

        // load V tile into KVs (overwrite K)
        const float* Vt = Vb + (size_t)(kt * 64) * HD;
#pragma unroll
        for (int it = 0; it < 4; it++) {
            int lin = tid + it * 256;
            int row = lin >> 4;
            int c4  = lin & 15;
            *(float4*)&KVs[row * FST + c4 * 4] =
                *(const float4*)&Vt[(size_t)row * HD + c4 * 4];
        }
        __syncthreads();

        // O = O*corr + P @ V   (rows = queries, cols = d = tx*4+j)
#pragma unroll
        for (int i = 0; i < 4; i++)
#pragma unroll
            for (int j = 0; j < 4; j++) o[i][j] *= corr[i];

#pragma unroll
        for (int k4 = 0; k4 < 16; k4++) {
            float4 a[4];
#pragma unroll
            for (int i = 0; i < 4; i++)
                a[i] = *(const float4*)&Ps[(ty * 4 + i) * FST + k4 * 4];
#pragma unroll
            for (int c = 0; c < 4; c++) {
                float4 bv = *(const float4*)&KVs[(k4 * 4 + c) * FST + tx * 4];
#pragma unroll
                for (int i = 0; i < 4; i++) {
                    float av = (c == 0) ? a[i].x : (c == 1) ? a[i].y
                               : (c == 2) ? a[i].z : a[i].w;
                    o[i][0] += av * bv.x;
                    o[i][1] += av * bv.y;
                    o[i][2] += av * bv.z;
                    o[i][3] += av * bv.w;
                }
            }
        }
        __syncthreads();   // V + P reads done before next K load
    }

    // epilogue -> g_ao [B,S,D] with D index = h*64 + d
#pragma unroll
    for (int i = 0; i < 4; i++) {
        float inv = 1.f / lrow[i];
        int srow = q0 + ty * 4 + i;
        float* dst = g_ao + ((size_t)b * SS + srow) * DD + h * HD + tx * 4;
        dst[0] = o[i][0] * inv;
        dst[1] = o[i][1] * inv;
        dst[2] = o[i][2] * inv;
        dst[3] = o[i][3] * inv;
    }
}

// ---------------------------------------------------------------------------
extern "C" void kernel_launch(void* const* d_in, const int* in_sizes, int n_in,
                              void* d_out, int out_size)
{
    const float* q  = (const float*)d_in[0];
    const float* k  = (const float*)d_in[1];
    const float* v  = (const float*)d_in[2];
    const float* Wq = (const float*)d_in[3];
    const float* bq = (const float*)d_in[4];
    const float* Wk = (const float*)d_in[5];
    const float* bk = (const float*)d_in[6];
    const float* Wv = (const float*)d_in[7];
    const float* bv = (const float*)d_in[8];
    const float* Wo = (const float*)d_in[9];
    const float* bo = (const float*)d_in[10];
    float* out = (float*)d_out;

    cudaFuncSetAttribute(flash_kernel,
                         cudaFuncAttributeMaxDynamicSharedMemorySize, FLASH_SMEM);

    dim3 pgrid(DD / 128, (BB * SS) / 128);   // (8, 32)
    proj_gemm<0><<<pgrid, 256>>>(q, Wq, bq, nullptr);
    proj_gemm<1><<<pgrid, 256>>>(k, Wk, bk, nullptr);
    proj_gemm<2><<<pgrid, 256>>>(v, Wv, bv, nullptr);

    flash_kernel<<<dim3(SS / 64, HH, BB), 256, FLASH_SMEM>>>();

    // final projection reads g_ao; pass its symbol via a tiny helper kernel-free
    // trick: proj_gemm<3> takes X as a parameter, so we need the device address.
    // g_ao is a device symbol in this TU; take its address via a device-visible
    // constant resolved at launch using cudaGetSymbolAddress (non-stream API,
    // capture-safe, no allocation).
    void* p_ao = nullptr;
    cudaGetSymbolAddress(&p_ao, g_ao);
    proj_gemm<3><<<pgrid, 256>>>((const float*)p_ao, Wo, bo, out);
}

// round 5
// speedup vs baseline: 5.3488x; 5.3488x over previous
#include <cuda_runtime.h>
#include <cstdint>

// Problem constants
#define BB   2
#define SS   2048
#define DD   1024
#define HH   16
#define HD   64
#define QK_SCALE 0.125f      // 1/sqrt(64)

// ---------------- scratch (device globals; no allocation allowed) ----------
__device__ float g_qh[BB*HH*SS*HD];   // [B,H,S,HD]
__device__ float g_kh[BB*HH*SS*HD];
__device__ float g_vh[BB*HH*SS*HD];
__device__ float g_ao[BB*SS*DD];      // attention output, [B,S,D]

// ---------------------------------------------------------------------------
// helpers
// ---------------------------------------------------------------------------
__device__ __forceinline__ float to_tf32(float x) {
    float y;
    asm("cvt.rna.tf32.f32 %0, %1;" : "=f"(y) : "f"(x));
    return y;
}

__device__ __forceinline__ float4 to_tf32_4(float4 v) {
    v.x = to_tf32(v.x); v.y = to_tf32(v.y);
    v.z = to_tf32(v.z); v.w = to_tf32(v.w);
    return v;
}

// D = A(16x8,row) * B(8x8,col) + D, tf32 inputs, f32 accum
__device__ __forceinline__ void mma_tf32(float* d, const float* a, const float* b) {
    asm volatile(
        "mma.sync.aligned.m16n8k8.row.col.f32.tf32.tf32.f32 "
        "{%0,%1,%2,%3}, {%4,%5,%6,%7}, {%8,%9}, {%0,%1,%2,%3};"
        : "+f"(d[0]), "+f"(d[1]), "+f"(d[2]), "+f"(d[3])
        : "r"(__float_as_uint(a[0])), "r"(__float_as_uint(a[1])),
          "r"(__float_as_uint(a[2])), "r"(__float_as_uint(a[3])),
          "r"(__float_as_uint(b[0])), "r"(__float_as_uint(b[1])));
}

// ---------------------------------------------------------------------------
// Projection GEMM (TF32 mma): Y = X @ W^T + b
//   X: [4096,1024] rm, W: [1024,1024] rm (out-features major)
// CTA 128x128, 256 thr (8 warps), warp tile 32x64, BK=32.
// TGT: 0->g_qh 1->g_kh 2->g_vh (head-split), 3->Yp plain [M,N]
// ---------------------------------------------------------------------------
#define PST 36   // smem row stride (floats)

template<int TGT>
__global__ __launch_bounds__(256) void proj_mma(const float* __restrict__ X,
                                                const float* __restrict__ W,
                                                const float* __restrict__ bias,
                                                float* __restrict__ Yp)
{
    __shared__ float As[128][PST];
    __shared__ float Bs[128][PST];

    const int m0   = blockIdx.y * 128;
    const int n0   = blockIdx.x * 128;
    const int tid  = threadIdx.x;
    const int wid  = tid >> 5;
    const int lane = tid & 31;
    const int wm   = wid >> 1;      // 0..3 : row block of 32
    const int wn   = wid & 1;       // 0..1 : col block of 64
    const int r    = lane >> 2;     // group id 0..7
    const int q    = lane & 3;      // thread-in-group 0..3

    float acc[2][8][4];
#pragma unroll
    for (int mt = 0; mt < 2; mt++)
#pragma unroll
        for (int j = 0; j < 8; j++)
#pragma unroll
            for (int c = 0; c < 4; c++) acc[mt][j][c] = 0.f;

    for (int k0 = 0; k0 < DD; k0 += 32) {
        // load 128x32 of X and W, converting to tf32 (rna)
#pragma unroll
        for (int it = 0; it < 4; it++) {
            int lin = tid + it * 256;   // 0..1023 float4 slots
            int row = lin >> 3;
            int c4  = lin & 7;
            float4 av = *(const float4*)&X[(size_t)(m0 + row) * DD + k0 + c4 * 4];
            *(float4*)&As[row][c4 * 4] = to_tf32_4(av);
            float4 bv = *(const float4*)&W[(size_t)(n0 + row) * DD + k0 + c4 * 4];
            *(float4*)&Bs[row][c4 * 4] = to_tf32_4(bv);
        }
        __syncthreads();

#pragma unroll
        for (int ks = 0; ks < 4; ks++) {
            float a[2][4], b[8][2];
#pragma unroll
            for (int mt = 0; mt < 2; mt++) {
                int row = wm * 32 + mt * 16 + r;
                a[mt][0] = As[row][ks * 8 + q];
                a[mt][1] = As[row + 8][ks * 8 + q];
                a[mt][2] = As[row][ks * 8 + q + 4];
                a[mt][3] = As[row + 8][ks * 8 + q + 4];
            }
#pragma unroll
            for (int j = 0; j < 8; j++) {
                int row = wn * 64 + j * 8 + r;
                b[j][0] = Bs[row][ks * 8 + q];
                b[j][1] = Bs[row][ks * 8 + q + 4];
            }
#pragma unroll
            for (int mt = 0; mt < 2; mt++)
#pragma unroll
                for (int j = 0; j < 8; j++)
                    mma_tf32(acc[mt][j], a[mt], b[j]);
        }
        __syncthreads();
    }

    float* out = (TGT == 0) ? g_qh : (TGT == 1) ? g_kh : (TGT == 2) ? g_vh : Yp;

#pragma unroll
    for (int mt = 0; mt < 2; mt++) {
#pragma unroll
        for (int j = 0; j < 8; j++) {
            int n  = n0 + wn * 64 + j * 8 + 2 * q;
            float b0 = bias[n], b1 = bias[n + 1];
#pragma unroll
            for (int half = 0; half < 2; half++) {
                int m = m0 + wm * 32 + mt * 16 + r + half * 8;
                float y0 = acc[mt][j][half * 2 + 0] + b0;
                float y1 = acc[mt][j][half * 2 + 1] + b1;
                if (TGT < 3) {
                    int bb = m >> 11, s = m & 2047;
                    int h  = n >> 6,  d = n & 63;
                    float* dst = out + (((size_t)bb * HH + h) * SS + s) * HD + d;
                    *(float2*)dst = make_float2(y0, y1);
                } else {
                    *(float2*)&out[(size_t)m * DD + n] = make_float2(y0, y1);
                }
            }
        }
    }
}

// ---------------------------------------------------------------------------
// Flash attention with TF32 mma.
// Grid (S/64, H, B), 128 threads (4 warps). Q tile 64, key tiles 64, HD=64.
// Each warp owns 16 query rows (m16 x n64 of mma frags) -> softmax row stays
// inside one warp (shuffle over lane%4 group only).
// smem: Qs[64][68] Ks[64][68] Vs[64][68] Ps[64][68]  = 69632 B
// ---------------------------------------------------------------------------
#define FS 68
#define FLASH_SMEM (4 * 64 * FS * 4)

__global__ __launch_bounds__(128) void flash_mma()
{
    extern __shared__ float sm[];
    float* Qs = sm;
    float* Ks = sm + 64 * FS;
    float* Vs = sm + 2 * 64 * FS;
    float* Ps = sm + 3 * 64 * FS;

    const int q0   = blockIdx.x * 64;
    const int h    = blockIdx.y;
    const int b    = blockIdx.z;
    const int tid  = threadIdx.x;
    const int wid  = tid >> 5;
    const int lane = tid & 31;
    const int r    = lane >> 2;
    const int q    = lane & 3;
    const int wrow = wid * 16;          // warp's query-row base within tile

    const float* Qb = g_qh + ((size_t)(b * HH + h) * SS) * HD;
    const float* Kb = g_kh + ((size_t)(b * HH + h) * SS) * HD;
    const float* Vb = g_vh + ((size_t)(b * HH + h) * SS) * HD;

    // load Q tile, pre-scaled, tf32-rounded
#pragma unroll
    for (int it = 0; it < 8; it++) {
        int lin = tid + it * 128;       // 1024 float4 slots
        int row = lin >> 4;
        int c4  = lin & 15;
        float4 v = *(const float4*)&Qb[(size_t)(q0 + row) * HD + c4 * 4];
        v.x *= QK_SCALE; v.y *= QK_SCALE; v.z *= QK_SCALE; v.w *= QK_SCALE;
        *(float4*)&Qs[row * FS + c4 * 4] = to_tf32_4(v);
    }

    float o[8][4];
#pragma unroll
    for (int j = 0; j < 8; j++)
#pragma unroll
        for (int c = 0; c < 4; c++) o[j][c] = 0.f;
    float m0_ = -1e30f, m1_ = -1e30f, l0 = 0.f, l1 = 0.f;

    for (int kt = 0; kt < SS / 64; kt++) {
        const float* Kt = Kb + (size_t)(kt * 64) * HD;
        const float* Vt = Vb + (size_t)(kt * 64) * HD;
#pragma unroll
        for (int it = 0; it < 8; it++) {
            int lin = tid + it * 128;
            int row = lin >> 4;
            int c4  = lin & 15;
            *(float4*)&Ks[row * FS + c4 * 4] =
                to_tf32_4(*(const float4*)&Kt[(size_t)row * HD + c4 * 4]);
            *(float4*)&Vs[row * FS + c4 * 4] =
                to_tf32_4(*(const float4*)&Vt[(size_t)row * HD + c4 * 4]);
        }
        __syncthreads();

        // ---- S = Q K^T : warp rows [wrow, wrow+16), all 64 keys
        float s[8][4];
#pragma unroll
        for (int j = 0; j < 8; j++)
#pragma unroll
            for (int c = 0; c < 4; c++) s[j][c] = 0.f;

#pragma unroll
        for (int ks = 0; ks < 8; ks++) {
            float a[4];
            a[0] = Qs[(wrow + r) * FS + ks * 8 + q];
            a[1] = Qs[(wrow + r + 8) * FS + ks * 8 + q];
            a[2] = Qs[(wrow + r) * FS + ks * 8 + q + 4];
            a[3] = Qs[(wrow + r + 8) * FS + ks * 8 + q + 4];
#pragma unroll
            for (int j = 0; j < 8; j++) {
                float bfr[2];
                bfr[0] = Ks[(j * 8 + r) * FS + ks * 8 + q];
                bfr[1] = Ks[(j * 8 + r) * FS + ks * 8 + q + 4];
                mma_tf32(s[j], a, bfr);
            }
        }

        // ---- online softmax (rows wrow+r and wrow+r+8; partners = lane%4 group)
        float t0 = -1e30f, t1 = -1e30f;
#pragma unroll
        for (int j = 0; j < 8; j++) {
            t0 = fmaxf(t0, fmaxf(s[j][0], s[j][1]));
            t1 = fmaxf(t1, fmaxf(s[j][2], s[j][3]));
        }
#pragma unroll
        for (int msk = 1; msk <= 2; msk <<= 1) {
            t0 = fmaxf(t0, __shfl_xor_sync(0xffffffffu, t0, msk));
            t1 = fmaxf(t1, __shfl_xor_sync(0xffffffffu, t1, msk));
        }
        float nm0 = fmaxf(m0_, t0), nm1 = fmaxf(m1_, t1);
        float corr0 = __expf(m0_ - nm0), corr1 = __expf(m1_ - nm1);
        m0_ = nm0; m1_ = nm1;

        float rs0 = 0.f, rs1 = 0.f;
#pragma unroll
        for (int j = 0; j < 8; j++) {
            s[j][0] = __expf(s[j][0] - nm0);
            s[j][1] = __expf(s[j][1] - nm0);
            s[j][2] = __expf(s[j][2] - nm1);
            s[j][3] = __expf(s[j][3] - nm1);
            rs0 += s[j][0] + s[j][1];
            rs1 += s[j][2] + s[j][3];
        }
#pragma unroll
        for (int msk = 1; msk <= 2; msk <<= 1) {
            rs0 += __shfl_xor_sync(0xffffffffu, rs0, msk);
            rs1 += __shfl_xor_sync(0xffffffffu, rs1, msk);
        }
        l0 = l0 * corr0 + rs0;
        l1 = l1 * corr1 + rs1;

        // stage P (tf32-rounded), C-fragment -> row-major smem
#pragma unroll
        for (int j = 0; j < 8; j++) {
            *(float2*)&Ps[(wrow + r) * FS + j * 8 + 2 * q] =
                make_float2(to_tf32(s[j][0]), to_tf32(s[j][1]));
            *(float2*)&Ps[(wrow + r + 8) * FS + j * 8 + 2 * q] =
                make_float2(to_tf32(s[j][2]), to_tf32(s[j][3]));
        }

        // rescale O by correction factors
#pragma unroll
        for (int j = 0; j < 8; j++) {
            o[j][0] *= corr0; o[j][1] *= corr0;
            o[j][2] *= corr1; o[j][3] *= corr1;
        }
        __syncthreads();

        // ---- O += P @ V  (A = Ps rows [wrow,wrow+16), B = Vs k-major)
#pragma unroll
        for (int ks = 0; ks < 8; ks++) {
            float a[4];
            a[0] = Ps[(wrow + r) * FS + ks * 8 + q];
            a[1] = Ps[(wrow + r + 8) * FS + ks * 8 + q];
            a[2] = Ps[(wrow + r) * FS + ks * 8 + q + 4];
            a[3] = Ps[(wrow + r + 8) * FS + ks * 8 + q + 4];
#pragma unroll
            for (int j = 0; j < 8; j++) {
                float bfr[2];
                bfr[0] = Vs[(ks * 8 + q) * FS + j * 8 + r];
                bfr[1] = Vs[(ks * 8 + q + 4) * FS + j * 8 + r];
                mma_tf32(o[j], a, bfr);
            }
        }
        __syncthreads();   // all Vs/Ks reads done before next tile load
    }

    // epilogue: normalize and write to g_ao [B,S,D], D-col = h*64 + n
    float inv0 = 1.f / l0, inv1 = 1.f / l1;
#pragma unroll
    for (int j = 0; j < 8; j++) {
        int col = h * HD + j * 8 + 2 * q;
        int s0  = q0 + wrow + r;
        float* d0 = g_ao + ((size_t)b * SS + s0) * DD + col;
        *(float2*)d0 = make_float2(o[j][0] * inv0, o[j][1] * inv0);
        float* d1 = g_ao + ((size_t)b * SS + s0 + 8) * DD + col;
        *(float2*)d1 = make_float2(o[j][2] * inv1, o[j][3] * inv1);
    }
}

// ---------------------------------------------------------------------------
extern "C" void kernel_launch(void* const* d_in, const int* in_sizes, int n_in,
                              void* d_out, int out_size)
{
    const float* q  = (const float*)d_in[0];
    const float* k  = (const float*)d_in[1];
    const float* v  = (const float*)d_in[2];
    const float* Wq = (const float*)d_in[3];
    const float* bq = (const float*)d_in[4];
    const float* Wk = (const float*)d_in[5];
    const float* bk = (const float*)d_in[6];
    const float* Wv = (const float*)d_in[7];
    const float* bv = (const float*)d_in[8];
    const float* Wo = (const float*)d_in[9];
    const float* bo = (const float*)d_in[10];
    float* out = (float*)d_out;

    cudaFuncSetAttribute(flash_mma,
                         cudaFuncAttributeMaxDynamicSharedMemorySize, FLASH_SMEM);

    dim3 pgrid(DD / 128, (BB * SS) / 128);   // (8, 32)
    proj_mma<0><<<pgrid, 256>>>(q, Wq, bq, nullptr);
    proj_mma<1><<<pgrid, 256>>>(k, Wk, bk, nullptr);
    proj_mma<2><<<pgrid, 256>>>(v, Wv, bv, nullptr);

    flash_mma<<<dim3(SS / 64, HH, BB), 128, FLASH_SMEM>>>();

    void* p_ao = nullptr;
    cudaGetSymbolAddress(&p_ao, g_ao);
    proj_mma<3><<<pgrid, 256>>>((const float*)p_ao, Wo, bo, out);
}